// round 8
// baseline (speedup 1.0000x reference)
#include <cuda_runtime.h>
#include <cuda_bf16.h>

#define HID 256
#define GAMMA_F 12.0f
#define BATCH 8
#define TILE_ROWS 32
#define RPAD 260          // padded row stride (floats): banks (4r+j)%32 distinct
#define NE_MAX 100000

typedef unsigned long long u64;

// Transposed scores: S_T[b][e], 8 planes of 400KB (3.2MB total, L2-resident).
__device__ float g_scores_t[BATCH * NE_MAX];

__device__ __forceinline__ u64 fadd2(u64 a, u64 b) {
    u64 d;
    asm("add.rn.f32x2 %0, %1, %2;" : "=l"(d) : "l"(a), "l"(b));
    return d;
}
__device__ __forceinline__ float2 unpack2(u64 v) {
    float2 r;
    asm("mov.b64 {%0, %1}, %2;" : "=f"(r.x), "=f"(r.y) : "l"(v));
    return r;
}
#define ABSMASK2 0x7FFFFFFF7FFFFFFFULL

// ---------------------------------------------------------------------------
// Kernel 1: thread-per-(row,batch). Block stages 32 rows into SMEM, each
// thread scores one (row,batch) pair over all 256 dims. No shuffles at all.
// ---------------------------------------------------------------------------
__global__ void __launch_bounds__(256)
score_kernel(const float* __restrict__ ent,
             const float* __restrict__ rel,
             const int*   __restrict__ pos,
             float*       __restrict__ scores_t,
             int ne)
{
    __shared__ float s_rows[TILE_ROWS][RPAD];   // 33.3 KB
    __shared__ float s_hrn[BATCH][RPAD];        //  8.3 KB

    const int tid = threadIdx.x;

    // Build NEGATED hr in SMEM once per block: |hr - e| == |e + (-hr)|.
    for (int i = tid; i < BATCH * HID; i += 256) {
        const int b = i >> 8, j = i & 255;
        const int hidx = pos[b * 3 + 0];
        const int ridx = pos[b * 3 + 1];
        s_hrn[b][j] = -(ent[(size_t)hidx * HID + j] + rel[(size_t)ridx * HID + j]);
    }
    __syncthreads();

    const int b = tid & 7;       // batch
    const int r = tid >> 3;      // row within tile
    const int ntiles = (ne + TILE_ROWS - 1) / TILE_ROWS;

    for (int tile = blockIdx.x; tile < ntiles; tile += gridDim.x) {
        const int row0 = tile * TILE_ROWS;

        // Stage 32 rows (32KB) coalesced: 2048 float4, 8 per thread.
        for (int i = tid; i < TILE_ROWS * (HID / 4); i += 256) {
            const int rr = i >> 6;          // 64 float4 per row
            const int cc = i & 63;
            if (row0 + rr < ne) {
                const float4 v =
                    reinterpret_cast<const float4*>(ent + (size_t)(row0 + rr) * HID)[cc];
                *reinterpret_cast<float4*>(&s_rows[rr][cc * 4]) = v;
            }
        }
        __syncthreads();

        const int row = row0 + r;
        if (row < ne) {
            const u64* e2 = reinterpret_cast<const u64*>(s_rows[r]);   // 128 pairs
            const u64* h2 = reinterpret_cast<const u64*>(s_hrn[b]);
            u64 a0 = 0, a1 = 0, a2 = 0, a3 = 0;
#pragma unroll
            for (int q = 0; q < HID / 2; q += 4) {
                const u64 d0 = fadd2(e2[q + 0], h2[q + 0]);
                const u64 d1 = fadd2(e2[q + 1], h2[q + 1]);
                const u64 d2 = fadd2(e2[q + 2], h2[q + 2]);
                const u64 d3 = fadd2(e2[q + 3], h2[q + 3]);
                a0 = fadd2(a0, d0 & ABSMASK2);
                a1 = fadd2(a1, d1 & ABSMASK2);
                a2 = fadd2(a2, d2 & ABSMASK2);
                a3 = fadd2(a3, d3 & ABSMASK2);
            }
            a0 = fadd2(fadd2(a0, a1), fadd2(a2, a3));
            const float2 f = unpack2(a0);
            scores_t[(size_t)b * ne + row] = GAMMA_F - (f.x + f.y);
        }
        __syncthreads();   // protect s_rows before next tile restage
    }
}

// ---------------------------------------------------------------------------
// Kernel 2: out[b][n] = S_T[b][neg[b][n]]. Random 4B reads inside one 400KB
// plane per batch -> L2-resident + high L1 hit rate.
// ---------------------------------------------------------------------------
__global__ void __launch_bounds__(128)
gather_kernel(const float* __restrict__ scores_t,
              const int*   __restrict__ neg,
              float*       __restrict__ out,
              int ne, int nneg)
{
    const int b = blockIdx.y;
    const int t = blockIdx.x * 128 + threadIdx.x;
    const int n4 = nneg >> 2;
    const float* plane = scores_t + (size_t)b * ne;

    if (t < n4) {
        const int4 idx = reinterpret_cast<const int4*>(neg + (size_t)b * nneg)[t];
        float4 r;
        r.x = __ldg(plane + idx.x);
        r.y = __ldg(plane + idx.y);
        r.z = __ldg(plane + idx.z);
        r.w = __ldg(plane + idx.w);
        reinterpret_cast<float4*>(out + (size_t)b * nneg)[t] = r;
    }
    // Scalar tail (nneg % 4), handled by first threads of block 0.
    const int tail = nneg - n4 * 4;
    if (blockIdx.x == 0 && threadIdx.x < tail) {
        const int n = n4 * 4 + threadIdx.x;
        out[(size_t)b * nneg + n] = __ldg(plane + neg[(size_t)b * nneg + n]);
    }
}

extern "C" void kernel_launch(void* const* d_in, const int* in_sizes, int n_in,
                              void* d_out, int out_size)
{
    const float* ent = (const float*)d_in[0];  // [NE, 256] f32
    const float* rel = (const float*)d_in[1];  // [NR, 256] f32
    const int*   pos = (const int*)d_in[2];    // [B, 3] i32
    const int*   neg = (const int*)d_in[3];    // [B, N] i32
    float*       out = (float*)d_out;          // [B, N] f32

    const int batch = in_sizes[2] / 3;         // 8
    const int nneg  = in_sizes[3] / batch;     // 100000
    const int ne    = in_sizes[0] / HID;       // 100000
    (void)batch;

    float* scores_t;
    cudaGetSymbolAddress((void**)&scores_t, g_scores_t);

    const int ntiles = (ne + TILE_ROWS - 1) / TILE_ROWS;     // 3125
    const int nblk   = ntiles < 740 ? ntiles : 740;          // 5 CTA/SM x 148
    score_kernel<<<nblk, 256>>>(ent, rel, pos, scores_t, ne);

    dim3 g2((nneg / 4 + 127) / 128, BATCH);
    gather_kernel<<<g2, 128>>>(scores_t, neg, out, ne, nneg);
}